// round 16
// baseline (speedup 1.0000x reference)
#include <cuda_runtime.h>
#include <math.h>

#define NN    50000
#define FI    20
#define HIDD  500
#define NOUT  2
#define NPAIR 210            // upper-triangular (incl. diag) pairs of 20
#define BN_EPS 1e-5f
#define CH    125            // nodes per gather block (400 blocks: 2.7/SM TLP)
#define NB    (NN / CH)      // 400
#define NB2   196            // k_final blocks: 196*256 >= 50000
#define PAD   64             // padded-CSR width (deg ~ Poisson(16))
#define OVFC  4096           // overflow capacity (general-correctness fallback)

// ---- scratch (__device__ globals, zero-initialized; self-cleaning) ----
static __device__ int            g_cnt[NN];        // degree counts (zeroed in k_final)
static __device__ unsigned short g_slots[PAD * NN];// slot-major CSR: slots[j*NN+c]=row
static __device__ int            g_ovfn;           // overflow count (zeroed by last gather block)
static __device__ int2           g_ovf[OVFC];      // overflow (row,col) pairs
static __device__ float4         g_agg4[NN * 5];   // aggX = dinv_c*(sum + Xs_c)
static __device__ double         g_m[FI];          // column sums of aggX
static __device__ double         g_G[NPAIR];       // upper-tri Gram aggX^T aggX
static __device__ int            g_c;              // gather arrival counter
static __device__ float          g_M2[FI * NOUT];  // folded 20x2 head matrix
static __device__ float          g_C[NOUT];        // folded bias

// K1: build slot-major padded CSR (4 edges/thread; R13's measured-best shape)
__global__ void __launch_bounds__(256) k_build(const int* __restrict__ ei, int E) {
    int t = blockIdx.x * blockDim.x + threadIdx.x;
    int e = 4 * t;
    if (e + 3 < E) {
        int4 r4 = *(const int4*)(ei + e);
        int4 c4 = *(const int4*)(ei + E + e);
        int rr[4] = {r4.x, r4.y, r4.z, r4.w};
        int cc[4] = {c4.x, c4.y, c4.z, c4.w};
#pragma unroll
        for (int k = 0; k < 4; k++) {
            int pos = atomicAdd(&g_cnt[cc[k]], 1);
            if (pos < PAD) g_slots[pos * NN + cc[k]] = (unsigned short)rr[k];
            else {
                int o = atomicAdd(&g_ovfn, 1);
                if (o < OVFC) g_ovf[o] = make_int2(rr[k], cc[k]);
            }
        }
    } else {
        for (int k = e; k < E; k++) {
            int r = ei[k], c = ei[E + k];
            int pos = atomicAdd(&g_cnt[c], 1);
            if (pos < PAD) g_slots[pos * NN + c] = (unsigned short)r;
            else {
                int o = atomicAdd(&g_ovfn, 1);
                if (o < OVFC) g_ovf[o] = make_int2(r, c);
            }
        }
    }
}

// K2: gather (1 thread/node, slot-major coalesced indices, MLP x2),
//     stats, and last-arriving-block BN fold -> g_M2/g_C/rsu.
__global__ void __launch_bounds__(256) k_gather(
                       const float* __restrict__ X,      // node_feature [NN,20]
                       const float* __restrict__ W,      // gcn_W  [20,500]
                       const float* __restrict__ b,      // gcn_b  [500]
                       const float* __restrict__ gamma,  // [500]
                       const float* __restrict__ beta,   // [500]
                       const float* __restrict__ W2,     // lin_W  [500,2]
                       const float* __restrict__ lb,     // lin_b  [2]
                       float* __restrict__ out) {        // [NN*2 | 500 rsu]
    __shared__ float s[CH * 21];               // stride 21: conflict-free
    __shared__ int   isLast;
    __shared__ float smm[FI];
    __shared__ float sGfull[FI][FI + 1];
    __shared__ float sRed[8][42];              // per-warp fold partials
    int t = threadIdx.x;                       // 256 threads (125 gather)
    int n0 = blockIdx.x * CH;
    int ovfn = g_ovfn;                         // 0 on this input

    if (t < CH) {
        int n = n0 + t;
        int deg = g_cnt[n];                    // NOT zeroed here (k_final cleans)
        float acc[FI];
#pragma unroll
        for (int k = 0; k < FI; k++) acc[k] = 0.f;
        int m = deg < PAD ? deg : PAD;
        int j = 0;
        for (; j + 1 < m; j += 2) {            // MLP x2: two independent chains
            int r1 = (int)g_slots[j * NN + n];
            int r2 = (int)g_slots[(j + 1) * NN + n];
            float d1 = rsqrtf((float)(g_cnt[r1] + 1));
            float d2 = rsqrtf((float)(g_cnt[r2] + 1));
            const float4* x1 = (const float4*)(X + r1 * FI);
            const float4* x2 = (const float4*)(X + r2 * FI);
#pragma unroll
            for (int k = 0; k < 5; k++) {
                float4 u = __ldg(x1 + k);
                float4 v = __ldg(x2 + k);
                acc[4*k+0] += d1*u.x + d2*v.x;
                acc[4*k+1] += d1*u.y + d2*v.y;
                acc[4*k+2] += d1*u.z + d2*v.z;
                acc[4*k+3] += d1*u.w + d2*v.w;
            }
        }
        if (j < m) {
            int r1 = (int)g_slots[j * NN + n];
            float d1 = rsqrtf((float)(g_cnt[r1] + 1));
            const float4* x1 = (const float4*)(X + r1 * FI);
#pragma unroll
            for (int k = 0; k < 5; k++) {
                float4 u = __ldg(x1 + k);
                acc[4*k+0] += d1*u.x; acc[4*k+1] += d1*u.y;
                acc[4*k+2] += d1*u.z; acc[4*k+3] += d1*u.w;
            }
        }
        if (ovfn > 0) {                        // rare general-correctness path
            int L = ovfn < OVFC ? ovfn : OVFC;
            for (int o = 0; o < L; o++) {
                int2 rc = g_ovf[o];
                if (rc.y == n) {
                    float dr = rsqrtf((float)(g_cnt[rc.x] + 1));
                    const float* x1 = X + rc.x * FI;
#pragma unroll
                    for (int k = 0; k < FI; k++) acc[k] += dr * x1[k];
                }
            }
        }
        // self term + outer dinv scaling
        float d = rsqrtf((float)(deg + 1));
        const float* xn = X + n * FI;
        float4* ag = g_agg4 + n * 5;
        float* sr = s + t * 21;
#pragma unroll
        for (int k = 0; k < 5; k++) {
            float4 a;
            a.x = d * (acc[4*k+0] + d * xn[4*k+0]);
            a.y = d * (acc[4*k+1] + d * xn[4*k+1]);
            a.z = d * (acc[4*k+2] + d * xn[4*k+2]);
            a.w = d * (acc[4*k+3] + d * xn[4*k+3]);
            ag[k] = a;
            sr[4*k+0] = a.x; sr[4*k+1] = a.y;
            sr[4*k+2] = a.z; sr[4*k+3] = a.w;
        }
    }
    __syncthreads();

    // stats: fp32 partials over CH rows, double-atomic combine
    if (t < FI) {
        float b0 = 0.f;
        for (int n = 0; n < CH; n++) b0 += s[n * 21 + t];
        atomicAdd(&g_m[t], (double)b0);
    } else if (t < FI + NPAIR) {
        int p = t - FI, i = 0;
        while (p >= FI - i) { p -= FI - i; i++; }
        int j2 = i + p;
        float b0 = 0.f;
        for (int n = 0; n < CH; n++) b0 += s[n * 21 + i] * s[n * 21 + j2];
        atomicAdd(&g_G[t - FI], (double)b0);
    }
    __threadfence();
    __syncthreads();

    // ---- last-block election (nobody waits on this)
    if (t == 0) isLast = (atomicAdd(&g_c, 1) == NB - 1);
    __syncthreads();
    if (!isLast) return;
    __threadfence();                   // all blocks' stats now visible

    // ---- stage complete stats; self-clean
    if (t < FI) { smm[t] = (float)g_m[t]; g_m[t] = 0.0; }
    if (t < NPAIR) {
        int p = t, i = 0;
        while (p >= FI - i) { p -= FI - i; i++; }
        int j2 = i + p;
        float v = (float)g_G[t];
        g_G[t] = 0.0;
        sGfull[i][j2] = v;
        sGfull[j2][i] = v;
    }
    if (t == 0) { g_c = 0; g_ovfn = 0; }
    __syncthreads();

    // ---- fold: per-feature BN; M2 accumulated in registers from w[20]
    float a0row[FI];
#pragma unroll
    for (int i = 0; i < FI; i++) a0row[i] = ((const float*)g_agg4)[i];
    float m2loc[FI * NOUT];
#pragma unroll
    for (int k = 0; k < FI * NOUT; k++) m2loc[k] = 0.f;
    float c0 = 0.f, c1 = 0.f;
    for (int f = t; f < HIDD; f += 256) {
        float w[FI];
#pragma unroll
        for (int i = 0; i < FI; i++) w[i] = W[i * HIDD + f];
        float bf = b[f];
        float su = 0.f;
#pragma unroll
        for (int i = 0; i < FI; i++) su += smm[i] * w[i];
        float mean = (su + (float)NN * bf) * (1.f / (float)NN);
        float q = 0.f;
#pragma unroll 2
        for (int i = 0; i < FI; i++) {
            float qi = 0.f;
#pragma unroll
            for (int j2 = 0; j2 < FI; j2++) qi += sGfull[i][j2] * w[j2];
            q += qi * w[i];
        }
        float sos = q * (1.f / (float)NN) + 2.f * bf * su * (1.f / (float)NN) + bf * bf;
        float var = sos - mean * mean;
        float sc = gamma[f] * rsqrtf(var + BN_EPS);
        float tt = beta[f] - mean * sc;
        float w20 = W2[2 * f], w21 = W2[2 * f + 1];
        float y0 = sc * w20, y1 = sc * w21;
#pragma unroll
        for (int i = 0; i < FI; i++) {
            m2loc[2 * i]     += w[i] * y0;
            m2loc[2 * i + 1] += w[i] * y1;
        }
        float bst = bf * sc + tt;
        c0 += bst * w20;
        c1 += bst * w21;
        float u0 = 0.f;                // rsu_embedding (node 0)
#pragma unroll
        for (int i = 0; i < FI; i++) u0 += a0row[i] * w[i];
        out[NN * NOUT + f] = (u0 + bf) * sc + tt;
    }
#pragma unroll
    for (int off = 16; off > 0; off >>= 1) {
#pragma unroll
        for (int k = 0; k < FI * NOUT; k++)
            m2loc[k] += __shfl_down_sync(0xffffffffu, m2loc[k], off);
        c0 += __shfl_down_sync(0xffffffffu, c0, off);
        c1 += __shfl_down_sync(0xffffffffu, c1, off);
    }
    if ((t & 31) == 0) {
        int wid = t >> 5;
#pragma unroll
        for (int k = 0; k < FI * NOUT; k++) sRed[wid][k] = m2loc[k];
        sRed[wid][40] = c0;
        sRed[wid][41] = c1;
    }
    __syncthreads();
    if (t < 42) {
        float acc2 = 0.f;
#pragma unroll
        for (int k = 0; k < 8; k++) acc2 += sRed[k][t];
        if (t < FI * NOUT) g_M2[t] = acc2;
        else               g_C[t - FI * NOUT] = acc2 + lb[t - FI * NOUT];
    }
}

// K3: slim head + g_cnt cleanup (covers all nodes; build needs zeros next call)
__global__ void __launch_bounds__(256) k_final(float* __restrict__ out) {
    __shared__ float sM[FI * NOUT];
    __shared__ float sC[NOUT];
    int t = threadIdx.x;
    if (t < FI * NOUT) sM[t] = g_M2[t];
    if (t < NOUT)      sC[t] = g_C[t];
    __syncthreads();
    int n = blockIdx.x * 256 + t;
    if (n >= NN) return;
    g_cnt[n] = 0;                              // self-clean for next replay
    float p0 = sC[0], p1 = sC[1];
    const float4* ar = (const float4*)(g_agg4 + n * 5);
#pragma unroll
    for (int k = 0; k < 5; k++) {
        float4 v = ar[k];
        p0 += v.x * sM[(4*k+0)*NOUT] + v.y * sM[(4*k+1)*NOUT]
            + v.z * sM[(4*k+2)*NOUT] + v.w * sM[(4*k+3)*NOUT];
        p1 += v.x * sM[(4*k+0)*NOUT+1] + v.y * sM[(4*k+1)*NOUT+1]
            + v.z * sM[(4*k+2)*NOUT+1] + v.w * sM[(4*k+3)*NOUT+1];
    }
    float l0 = fmaxf(p0, 0.f), l1 = fmaxf(p1, 0.f);
    float mx = fmaxf(l0, l1);
    float e0 = expf(l0 - mx), e1 = expf(l1 - mx);
    float inv = 1.f / (e0 + e1);
    ((float2*)out)[n] = make_float2(e0 * inv, e1 * inv);
}

extern "C" void kernel_launch(void* const* d_in, const int* in_sizes, int n_in,
                              void* d_out, int out_size) {
    const float* X     = (const float*)d_in[0];   // node_feature [50000,20]
    const int*   ei    = (const int*)  d_in[1];   // edge_index   [2,E]
    const float* gcnW  = (const float*)d_in[2];   // [20,500]
    const float* gcnB  = (const float*)d_in[3];   // [500]
    const float* gamma = (const float*)d_in[4];   // [500]
    const float* beta  = (const float*)d_in[5];   // [500]
    const float* linW  = (const float*)d_in[6];   // [500,2]
    const float* linB  = (const float*)d_in[7];   // [2]
    float* out = (float*)d_out;                   // [NN*2 action_prob][500 rsu]

    int E = in_sizes[1] / 2;
    int eb4 = (E / 4 + 255) / 256 + 1;

    k_build<<<eb4, 256>>>(ei, E);
    k_gather<<<NB, 256>>>(X, gcnW, gcnB, gamma, beta, linW, linB, out);
    k_final<<<NB2, 256>>>(out);
}

// round 17
// speedup vs baseline: 1.0819x; 1.0819x over previous
#include <cuda_runtime.h>
#include <math.h>

#define NN    50000
#define FI    20
#define HIDD  500
#define NOUT  2
#define NPAIR 210            // upper-triangular (incl. diag) pairs of 20
#define BN_EPS 1e-5f
#define CH    250            // nodes per gather block (200 blocks)
#define NB    (NN / CH)      // 200
#define NB2   196            // k_final blocks: 196*256 >= 50000
#define PAD   64             // padded-CSR width (deg ~ Poisson(16))
#define OVFC  4096           // overflow capacity (general-correctness fallback)

// ---- scratch (__device__ globals, zero-initialized; self-cleaning) ----
static __device__ int            g_cnt[NN];        // degree counts (zeroed in k_final)
static __device__ unsigned short g_slots[PAD * NN];// slot-major CSR: slots[j*NN+c]=row
static __device__ int            g_ovfn;           // overflow count (zeroed by last gather block)
static __device__ int2           g_ovf[OVFC];      // overflow (row,col) pairs
static __device__ float4         g_agg4[NN * 5];   // aggX = dinv_c*(sum + Xs_c)
static __device__ double         g_m[FI];          // column sums of aggX
static __device__ double         g_G[NPAIR];       // upper-tri Gram aggX^T aggX
static __device__ int            g_c;              // gather arrival counter
static __device__ float          g_M2[FI * NOUT];  // folded 20x2 head matrix
static __device__ float          g_C[NOUT];        // folded bias

// K1: build slot-major padded CSR (4 edges/thread; measured-best shape)
__global__ void __launch_bounds__(256) k_build(const int* __restrict__ ei, int E) {
    int t = blockIdx.x * blockDim.x + threadIdx.x;
    int e = 4 * t;
    if (e + 3 < E) {
        int4 r4 = *(const int4*)(ei + e);
        int4 c4 = *(const int4*)(ei + E + e);
        int rr[4] = {r4.x, r4.y, r4.z, r4.w};
        int cc[4] = {c4.x, c4.y, c4.z, c4.w};
#pragma unroll
        for (int k = 0; k < 4; k++) {
            int pos = atomicAdd(&g_cnt[cc[k]], 1);
            if (pos < PAD) g_slots[pos * NN + cc[k]] = (unsigned short)rr[k];
            else {
                int o = atomicAdd(&g_ovfn, 1);
                if (o < OVFC) g_ovf[o] = make_int2(rr[k], cc[k]);
            }
        }
    } else {
        for (int k = e; k < E; k++) {
            int r = ei[k], c = ei[E + k];
            int pos = atomicAdd(&g_cnt[c], 1);
            if (pos < PAD) g_slots[pos * NN + c] = (unsigned short)r;
            else {
                int o = atomicAdd(&g_ovfn, 1);
                if (o < OVFC) g_ovf[o] = make_int2(r, c);
            }
        }
    }
}

// K2: gather (1 thread/node, slot-major coalesced indices, MLP x4),
//     stats, and last-arriving-block BN fold -> g_M2/g_C/rsu.
__global__ void __launch_bounds__(256) k_gather(
                       const float* __restrict__ X,      // node_feature [NN,20]
                       const float* __restrict__ W,      // gcn_W  [20,500]
                       const float* __restrict__ b,      // gcn_b  [500]
                       const float* __restrict__ gamma,  // [500]
                       const float* __restrict__ beta,   // [500]
                       const float* __restrict__ W2,     // lin_W  [500,2]
                       const float* __restrict__ lb,     // lin_b  [2]
                       float* __restrict__ out) {        // [NN*2 | 500 rsu]
    __shared__ float s[CH * 21];               // stride 21: conflict-free
    __shared__ int   isLast;
    __shared__ float smm[FI];
    __shared__ float sGfull[FI][FI + 1];
    __shared__ float sRed[8][42];              // per-warp fold partials
    int t = threadIdx.x;                       // 256 threads (250 gather)
    int n0 = blockIdx.x * CH;
    int ovfn = g_ovfn;                         // 0 on this input

    if (t < CH) {
        int n = n0 + t;
        int deg = g_cnt[n];                    // NOT zeroed here (k_final cleans)
        float acc[FI];
#pragma unroll
        for (int k = 0; k < FI; k++) acc[k] = 0.f;
        int m = deg < PAD ? deg : PAD;
        int j = 0;
        for (; j + 3 < m; j += 4) {            // MLP x4: 4 coalesced idx loads,
            int r1 = (int)g_slots[(j + 0) * NN + n];   // then 4 cnt + 20 X loads
            int r2 = (int)g_slots[(j + 1) * NN + n];   // all independent
            int r3 = (int)g_slots[(j + 2) * NN + n];
            int r4 = (int)g_slots[(j + 3) * NN + n];
            float d1 = rsqrtf((float)(g_cnt[r1] + 1));
            float d2 = rsqrtf((float)(g_cnt[r2] + 1));
            float d3 = rsqrtf((float)(g_cnt[r3] + 1));
            float d4 = rsqrtf((float)(g_cnt[r4] + 1));
            const float4* x1 = (const float4*)(X + r1 * FI);
            const float4* x2 = (const float4*)(X + r2 * FI);
            const float4* x3 = (const float4*)(X + r3 * FI);
            const float4* x4 = (const float4*)(X + r4 * FI);
#pragma unroll
            for (int k = 0; k < 5; k++) {
                float4 u = __ldg(x1 + k);
                float4 v = __ldg(x2 + k);
                float4 p = __ldg(x3 + k);
                float4 q = __ldg(x4 + k);
                acc[4*k+0] += d1*u.x + d2*v.x + d3*p.x + d4*q.x;
                acc[4*k+1] += d1*u.y + d2*v.y + d3*p.y + d4*q.y;
                acc[4*k+2] += d1*u.z + d2*v.z + d3*p.z + d4*q.z;
                acc[4*k+3] += d1*u.w + d2*v.w + d3*p.w + d4*q.w;
            }
        }
        for (; j < m; j++) {
            int r1 = (int)g_slots[j * NN + n];
            float d1 = rsqrtf((float)(g_cnt[r1] + 1));
            const float4* x1 = (const float4*)(X + r1 * FI);
#pragma unroll
            for (int k = 0; k < 5; k++) {
                float4 u = __ldg(x1 + k);
                acc[4*k+0] += d1*u.x; acc[4*k+1] += d1*u.y;
                acc[4*k+2] += d1*u.z; acc[4*k+3] += d1*u.w;
            }
        }
        if (ovfn > 0) {                        // rare general-correctness path
            int L = ovfn < OVFC ? ovfn : OVFC;
            for (int o = 0; o < L; o++) {
                int2 rc = g_ovf[o];
                if (rc.y == n) {
                    float dr = rsqrtf((float)(g_cnt[rc.x] + 1));
                    const float* x1 = X + rc.x * FI;
#pragma unroll
                    for (int k = 0; k < FI; k++) acc[k] += dr * x1[k];
                }
            }
        }
        // self term + outer dinv scaling
        float d = rsqrtf((float)(deg + 1));
        const float* xn = X + n * FI;
        float4* ag = g_agg4 + n * 5;
        float* sr = s + t * 21;
#pragma unroll
        for (int k = 0; k < 5; k++) {
            float4 a;
            a.x = d * (acc[4*k+0] + d * xn[4*k+0]);
            a.y = d * (acc[4*k+1] + d * xn[4*k+1]);
            a.z = d * (acc[4*k+2] + d * xn[4*k+2]);
            a.w = d * (acc[4*k+3] + d * xn[4*k+3]);
            ag[k] = a;
            sr[4*k+0] = a.x; sr[4*k+1] = a.y;
            sr[4*k+2] = a.z; sr[4*k+3] = a.w;
        }
    }
    __syncthreads();

    // stats: fp32 partials over CH rows, double-atomic combine
    if (t < FI) {
        float b0 = 0.f, b1 = 0.f;
        for (int n = 0; n < CH; n += 2) {
            b0 += s[n * 21 + t];
            b1 += s[(n + 1) * 21 + t];
        }
        atomicAdd(&g_m[t], (double)(b0 + b1));
    } else if (t < FI + NPAIR) {
        int p = t - FI, i = 0;
        while (p >= FI - i) { p -= FI - i; i++; }
        int j2 = i + p;
        float b0 = 0.f, b1 = 0.f;
        for (int n = 0; n < CH; n += 2) {
            b0 += s[n * 21 + i] * s[n * 21 + j2];
            b1 += s[(n + 1) * 21 + i] * s[(n + 1) * 21 + j2];
        }
        atomicAdd(&g_G[t - FI], (double)(b0 + b1));
    }
    __threadfence();
    __syncthreads();

    // ---- last-block election (nobody waits on this)
    if (t == 0) isLast = (atomicAdd(&g_c, 1) == NB - 1);
    __syncthreads();
    if (!isLast) return;
    __threadfence();                   // all blocks' stats now visible

    // ---- stage complete stats; self-clean
    if (t < FI) { smm[t] = (float)g_m[t]; g_m[t] = 0.0; }
    if (t < NPAIR) {
        int p = t, i = 0;
        while (p >= FI - i) { p -= FI - i; i++; }
        int j2 = i + p;
        float v = (float)g_G[t];
        g_G[t] = 0.0;
        sGfull[i][j2] = v;
        sGfull[j2][i] = v;
    }
    if (t == 0) { g_c = 0; g_ovfn = 0; }
    __syncthreads();

    // ---- fold: per-feature BN; M2 accumulated in registers from w[20]
    float a0row[FI];
#pragma unroll
    for (int i = 0; i < FI; i++) a0row[i] = ((const float*)g_agg4)[i];
    float m2loc[FI * NOUT];
#pragma unroll
    for (int k = 0; k < FI * NOUT; k++) m2loc[k] = 0.f;
    float c0 = 0.f, c1 = 0.f;
    for (int f = t; f < HIDD; f += 256) {
        float w[FI];
#pragma unroll
        for (int i = 0; i < FI; i++) w[i] = W[i * HIDD + f];
        float bf = b[f];
        float su = 0.f;
#pragma unroll
        for (int i = 0; i < FI; i++) su += smm[i] * w[i];
        float mean = (su + (float)NN * bf) * (1.f / (float)NN);
        float q = 0.f;
#pragma unroll 2
        for (int i = 0; i < FI; i++) {
            float qi = 0.f;
#pragma unroll
            for (int j2 = 0; j2 < FI; j2++) qi += sGfull[i][j2] * w[j2];
            q += qi * w[i];
        }
        float sos = q * (1.f / (float)NN) + 2.f * bf * su * (1.f / (float)NN) + bf * bf;
        float var = sos - mean * mean;
        float sc = gamma[f] * rsqrtf(var + BN_EPS);
        float tt = beta[f] - mean * sc;
        float w20 = W2[2 * f], w21 = W2[2 * f + 1];
        float y0 = sc * w20, y1 = sc * w21;
#pragma unroll
        for (int i = 0; i < FI; i++) {
            m2loc[2 * i]     += w[i] * y0;
            m2loc[2 * i + 1] += w[i] * y1;
        }
        float bst = bf * sc + tt;
        c0 += bst * w20;
        c1 += bst * w21;
        float u0 = 0.f;                // rsu_embedding (node 0)
#pragma unroll
        for (int i = 0; i < FI; i++) u0 += a0row[i] * w[i];
        out[NN * NOUT + f] = (u0 + bf) * sc + tt;
    }
#pragma unroll
    for (int off = 16; off > 0; off >>= 1) {
#pragma unroll
        for (int k = 0; k < FI * NOUT; k++)
            m2loc[k] += __shfl_down_sync(0xffffffffu, m2loc[k], off);
        c0 += __shfl_down_sync(0xffffffffu, c0, off);
        c1 += __shfl_down_sync(0xffffffffu, c1, off);
    }
    if ((t & 31) == 0) {
        int wid = t >> 5;
#pragma unroll
        for (int k = 0; k < FI * NOUT; k++) sRed[wid][k] = m2loc[k];
        sRed[wid][40] = c0;
        sRed[wid][41] = c1;
    }
    __syncthreads();
    if (t < 42) {
        float acc2 = 0.f;
#pragma unroll
        for (int k = 0; k < 8; k++) acc2 += sRed[k][t];
        if (t < FI * NOUT) g_M2[t] = acc2;
        else               g_C[t - FI * NOUT] = acc2 + lb[t - FI * NOUT];
    }
}

// K3: slim head + g_cnt cleanup (covers all nodes; build needs zeros next call)
__global__ void __launch_bounds__(256) k_final(float* __restrict__ out) {
    __shared__ float sM[FI * NOUT];
    __shared__ float sC[NOUT];
    int t = threadIdx.x;
    if (t < FI * NOUT) sM[t] = g_M2[t];
    if (t < NOUT)      sC[t] = g_C[t];
    __syncthreads();
    int n = blockIdx.x * 256 + t;
    if (n >= NN) return;
    g_cnt[n] = 0;                              // self-clean for next replay
    float p0 = sC[0], p1 = sC[1];
    const float4* ar = (const float4*)(g_agg4 + n * 5);
#pragma unroll
    for (int k = 0; k < 5; k++) {
        float4 v = ar[k];
        p0 += v.x * sM[(4*k+0)*NOUT] + v.y * sM[(4*k+1)*NOUT]
            + v.z * sM[(4*k+2)*NOUT] + v.w * sM[(4*k+3)*NOUT];
        p1 += v.x * sM[(4*k+0)*NOUT+1] + v.y * sM[(4*k+1)*NOUT+1]
            + v.z * sM[(4*k+2)*NOUT+1] + v.w * sM[(4*k+3)*NOUT+1];
    }
    float l0 = fmaxf(p0, 0.f), l1 = fmaxf(p1, 0.f);
    float mx = fmaxf(l0, l1);
    float e0 = expf(l0 - mx), e1 = expf(l1 - mx);
    float inv = 1.f / (e0 + e1);
    ((float2*)out)[n] = make_float2(e0 * inv, e1 * inv);
}

extern "C" void kernel_launch(void* const* d_in, const int* in_sizes, int n_in,
                              void* d_out, int out_size) {
    const float* X     = (const float*)d_in[0];   // node_feature [50000,20]
    const int*   ei    = (const int*)  d_in[1];   // edge_index   [2,E]
    const float* gcnW  = (const float*)d_in[2];   // [20,500]
    const float* gcnB  = (const float*)d_in[3];   // [500]
    const float* gamma = (const float*)d_in[4];   // [500]
    const float* beta  = (const float*)d_in[5];   // [500]
    const float* linW  = (const float*)d_in[6];   // [500,2]
    const float* linB  = (const float*)d_in[7];   // [2]
    float* out = (float*)d_out;                   // [NN*2 action_prob][500 rsu]

    int E = in_sizes[1] / 2;
    int eb4 = (E / 4 + 255) / 256 + 1;

    k_build<<<eb4, 256>>>(ei, E);
    k_gather<<<NB, 256>>>(X, gcnW, gcnB, gamma, beta, linW, linB, out);
    k_final<<<NB2, 256>>>(out);
}